// round 1
// baseline (speedup 1.0000x reference)
#include <cuda_runtime.h>
#include <cuda_bf16.h>

// AWingLoss with dilated-target mask, fused single pass + reduction.
// Layout: (B, C, H, W) = (32, 68, 128, 128) fp32, contiguous. W == H == 128.
// Mask: 3x3 grey dilation with symmetric pad=1 (== edge clamp), > 0.2 ? 11 : 1.

#define NBLOCKS 1184          // 148 SMs * 8
#define NTHREADS 256
#define WARPS_PER_BLOCK 8

__device__ double g_awing_sum;

__global__ void awing_zero_kernel() {
    g_awing_sum = 0.0;
}

__device__ __forceinline__ float awing_loss_px(float p, float y, float dil) {
    // e = alpha - y ; pow_t = 0.5^e = 2^(y - 2.1) ; pow_tm1 = 2 * pow_t
    float e     = 2.1f - y;
    float pow_t = exp2f(y - 2.1f);
    float omp   = 1.0f + pow_t;
    // A = 14 * (1/(1+pow_t)) * e * 2*pow_t
    float A = __fdividef(28.0f * e * pow_t, omp);
    // C = 0.5*A - 14*log1p(pow_t) ; pow_t in [0.23, 0.47] so logf(1+x) is safe
    float C = fmaf(0.5f, A, -14.0f * __logf(omp));
    float d = fabsf(p - y);
    // small branch side: 14*log1p(d^e), d < 0.5 so d^e < 0.47
    float l_small = 14.0f * __logf(1.0f + __powf(d, e));
    float l_big   = fmaf(A, d, -C);
    float l = (d < 0.5f) ? l_small : l_big;
    float m = (dil > 0.2f) ? 11.0f : 1.0f;
    return l * m;
}

__global__ void __launch_bounds__(NTHREADS)
awing_main_kernel(const float* __restrict__ pred,
                  const float* __restrict__ targ,
                  int rows)   // rows = B*C*H, each row is W=128 floats
{
    const int warp = threadIdx.x >> 5;
    const int lane = threadIdx.x & 31;
    const unsigned FULL = 0xffffffffu;

    float acc = 0.0f;

    for (int r0 = blockIdx.x * WARPS_PER_BLOCK; r0 < rows;
         r0 += gridDim.x * WARPS_PER_BLOCK) {
        int r = r0 + warp;
        if (r < rows) {
            int h = r & 127;                 // H = 128
            long long base = (long long)r << 7;   // r * 128
            long long up   = (h == 0)   ? base : base - 128;
            long long dn   = (h == 127) ? base : base + 128;
            int c = lane << 2;               // 4 pixels per lane, W = 128 = 32*4

            float4 p  = *reinterpret_cast<const float4*>(pred + base + c);
            float4 t  = *reinterpret_cast<const float4*>(targ + base + c);
            float4 tu = *reinterpret_cast<const float4*>(targ + up   + c);
            float4 td = *reinterpret_cast<const float4*>(targ + dn   + c);

            // vertical 3-max per column
            float4 v;
            v.x = fmaxf(t.x, fmaxf(tu.x, td.x));
            v.y = fmaxf(t.y, fmaxf(tu.y, td.y));
            v.z = fmaxf(t.z, fmaxf(tu.z, td.z));
            v.w = fmaxf(t.w, fmaxf(tu.w, td.w));

            // horizontal halo via shuffles (edge clamp at lane 0 / lane 31)
            float vL = __shfl_up_sync(FULL, v.w, 1);
            float vR = __shfl_down_sync(FULL, v.x, 1);
            if (lane == 0)  vL = v.x;
            if (lane == 31) vR = v.w;

            float d0 = fmaxf(vL,  fmaxf(v.x, v.y));
            float d1 = fmaxf(v.x, fmaxf(v.y, v.z));
            float d2 = fmaxf(v.y, fmaxf(v.z, v.w));
            float d3 = fmaxf(v.z, fmaxf(v.w, vR));

            acc += awing_loss_px(p.x, t.x, d0);
            acc += awing_loss_px(p.y, t.y, d1);
            acc += awing_loss_px(p.z, t.z, d2);
            acc += awing_loss_px(p.w, t.w, d3);
        }
    }

    // warp reduce
    #pragma unroll
    for (int o = 16; o > 0; o >>= 1)
        acc += __shfl_down_sync(FULL, acc, o);

    __shared__ float wsum[WARPS_PER_BLOCK];
    if (lane == 0) wsum[warp] = acc;
    __syncthreads();

    if (threadIdx.x == 0) {
        float s = 0.0f;
        #pragma unroll
        for (int i = 0; i < WARPS_PER_BLOCK; i++) s += wsum[i];
        atomicAdd(&g_awing_sum, (double)s);
    }
}

__global__ void awing_finalize_kernel(float* out, double inv_n) {
    out[0] = (float)(g_awing_sum * inv_n);
}

extern "C" void kernel_launch(void* const* d_in, const int* in_sizes, int n_in,
                              void* d_out, int out_size) {
    const float* pred = (const float*)d_in[0];
    const float* targ = (const float*)d_in[1];
    float* out = (float*)d_out;

    int n = in_sizes[0];          // B*C*H*W
    int rows = n >> 7;            // n / 128 (W = 128)
    double inv_n = 1.0 / (double)n;

    awing_zero_kernel<<<1, 1>>>();
    awing_main_kernel<<<NBLOCKS, NTHREADS>>>(pred, targ, rows);
    awing_finalize_kernel<<<1, 1>>>(out, inv_n);
}